// round 16
// baseline (speedup 1.0000x reference)
#include <cuda_runtime.h>
#include <cuda_fp16.h>
#include <mma.h>
#include <cstdint>

using namespace nvcuda;

#define Bb 32
#define Nn 4096
#define Mm 512
#define Cc 256
#define KF2 1056           // double-folded forward K (0..1024 data, pad to 33*32)

// ---------------------------------------------------------------------------
// Global scratch (static __device__ — no runtime allocation)
// ---------------------------------------------------------------------------
__device__ __align__(16) __half g_Af[(size_t)4 * 256 * KF2];
__device__ __align__(16) __half g_V4[(size_t)Bb * 4 * KF2 * Cc];
__device__ __align__(16) __half g_Ai[(size_t)4 * 1024 * 256];
__device__ __align__(16) __half g_Fre16[(size_t)Bb * Mm * Cc];
__device__ __align__(16) __half g_Fim16[(size_t)Bb * Mm * Cc];
__device__ __align__(16) __half g_G4[(size_t)Bb * 4 * 256 * 256];

// ---------------------------------------------------------------------------
__device__ __forceinline__ uint32_t s2u(const void* p) {
    uint32_t a;
    asm("{ .reg .u64 t; cvta.to.shared.u64 t, %1; cvt.u32.u64 %0, t; }"
        : "=r"(a) : "l"(p));
    return a;
}

#define CP16(dst, src) \
    asm volatile("cp.async.cg.shared.global [%0], [%1], 16;" :: "r"(dst), "l"(src))
#define CP_COMMIT() asm volatile("cp.async.commit_group;")
#define CP_WAIT3()  asm volatile("cp.async.wait_group 3;" ::: "memory")
#define CP_WAIT2()  asm volatile("cp.async.wait_group 2;" ::: "memory")
#define CP_WAIT1()  asm volatile("cp.async.wait_group 1;" ::: "memory")
#define CP_WAIT0()  asm volatile("cp.async.wait_group 0;" ::: "memory")

typedef wmma::fragment<wmma::matrix_a, 16, 16, 16, __half, wmma::row_major> FragA;
typedef wmma::fragment<wmma::matrix_b, 16, 16, 16, __half, wmma::row_major> FragB;
typedef wmma::fragment<wmma::accumulator, 16, 16, 16, float> FragC;

// ---------------------------------------------------------------------------
// Fused prep (one launch, permuted block order).
//   [0, 4224)       genA_fwd
//   [4224, 8320)    genA_inv
//   [8320, 16768)   packV4
// ---------------------------------------------------------------------------
#define PREP_BLOCKS 16768

__global__ __launch_bounds__(256) void prep_all(const float* __restrict__ v) {
    const int tid = threadIdx.x;
    unsigned u = (unsigned)(((unsigned long long)blockIdx.x * 9871ull) % PREP_BLOCKS);

    if (u < 4224u) {
        int idx = (int)u * 256 + tid;
        int comp = idx / (256 * KF2);
        int rem = idx - comp * (256 * KF2);
        int mp = rem / KF2, k = rem - mp * KF2;
        int m = 2 * mp + (comp & 1);
        float val = 0.0f;
        if (k <= 1024) {
            int t = (int)(((long long)m * k) & (Nn - 1));
            float s, c;
            sincospif((float)t * (1.0f / 2048.0f), &s, &c);
            val = (comp < 2) ? c : -s;
        }
        g_Af[idx] = __float2half(val);
    } else if (u < 8320u) {
        int idx = (int)(u - 4224u) * 256 + tid;
        int comp = idx >> 18;
        int rem = idx & 262143;
        int n = rem >> 8, mp = rem & 255;
        int m = 2 * mp + (comp & 1);
        int t = (int)(((long long)m * n) & (Nn - 1));
        float s, c;
        sincospif((float)t * (1.0f / 2048.0f), &s, &c);
        g_Ai[idx] = __float2half((comp < 2) ? c : s);
    } else {
        size_t idx4 = (size_t)(u - 8320u) * 256 + tid;
        int b = (int)(idx4 / (KF2 * 64));
        int rem = (int)(idx4 - (size_t)b * (KF2 * 64));
        int k = rem >> 6, i = (rem & 63) * 4;
        float4 pp, pm, mm_, mp;
        const float* vb = v + (size_t)b * Nn * Cc;
        if (k == 0) {
            float4 a = *(const float4*)(vb + i);
            float4 d = *(const float4*)(vb + (size_t)2048 * Cc + i);
            pp = make_float4(a.x + d.x, a.y + d.y, a.z + d.z, a.w + d.w);
            pm = make_float4(a.x - d.x, a.y - d.y, a.z - d.z, a.w - d.w);
            mm_ = make_float4(0.f, 0.f, 0.f, 0.f);
            mp = mm_;
        } else if (k < 1024) {
            float4 a = *(const float4*)(vb + (size_t)k * Cc + i);
            float4 bq = *(const float4*)(vb + (size_t)(Nn - k) * Cc + i);
            float4 c = *(const float4*)(vb + (size_t)(2048 - k) * Cc + i);
            float4 d = *(const float4*)(vb + (size_t)(2048 + k) * Cc + i);
            pp = make_float4(a.x + bq.x + c.x + d.x, a.y + bq.y + c.y + d.y,
                             a.z + bq.z + c.z + d.z, a.w + bq.w + c.w + d.w);
            pm = make_float4(a.x + bq.x - c.x - d.x, a.y + bq.y - c.y - d.y,
                             a.z + bq.z - c.z - d.z, a.w + bq.w - c.w - d.w);
            mm_ = make_float4(a.x - bq.x - c.x + d.x, a.y - bq.y - c.y + d.y,
                              a.z - bq.z - c.z + d.z, a.w - bq.w - c.w + d.w);
            mp = make_float4(a.x - bq.x + c.x - d.x, a.y - bq.y + c.y - d.y,
                             a.z - bq.z + c.z - d.z, a.w - bq.w + c.w - d.w);
        } else if (k == 1024) {
            float4 a = *(const float4*)(vb + (size_t)1024 * Cc + i);
            float4 d = *(const float4*)(vb + (size_t)3072 * Cc + i);
            pp = make_float4(a.x + d.x, a.y + d.y, a.z + d.z, a.w + d.w);
            mp = make_float4(a.x - d.x, a.y - d.y, a.z - d.z, a.w - d.w);
            pm = make_float4(0.f, 0.f, 0.f, 0.f);
            mm_ = pm;
        } else {
            pp = make_float4(0.f, 0.f, 0.f, 0.f);
            pm = pp; mm_ = pp; mp = pp;
        }
        size_t pbase = ((size_t)b * 4) * (KF2 * (size_t)Cc) + (size_t)k * Cc + i;
        const size_t PS = (size_t)KF2 * Cc;
        *(__half2*)(g_V4 + pbase)              = __half2{__float2half(pp.x), __float2half(pp.y)};
        *(__half2*)(g_V4 + pbase + 2)          = __half2{__float2half(pp.z), __float2half(pp.w)};
        *(__half2*)(g_V4 + pbase + PS)         = __half2{__float2half(pm.x), __float2half(pm.y)};
        *(__half2*)(g_V4 + pbase + PS + 2)     = __half2{__float2half(pm.z), __float2half(pm.w)};
        *(__half2*)(g_V4 + pbase + 2 * PS)     = __half2{__float2half(mm_.x), __float2half(mm_.y)};
        *(__half2*)(g_V4 + pbase + 2 * PS + 2) = __half2{__float2half(mm_.z), __float2half(mm_.w)};
        *(__half2*)(g_V4 + pbase + 3 * PS)     = __half2{__float2half(mp.x), __float2half(mp.y)};
        *(__half2*)(g_V4 + pbase + 3 * PS + 2) = __half2{__float2half(mp.z), __float2half(mp.w)};
    }
}

// ---------------------------------------------------------------------------
// Forward WMMA GEMM (double-folded, unchanged).
// ---------------------------------------------------------------------------
#define STAGE 27136

__global__ __launch_bounds__(512) void fwd_gemm() {
    extern __shared__ __align__(16) char sm[];
    const uint32_t sb = s2u(sm);
    const int tid = threadIdx.x;
    const int warp = tid >> 5, lane = tid & 31;
    const int wm = warp >> 2, wn = warp & 3;
    const int b = blockIdx.z;
    const int y = blockIdx.y;
    const int comp = y >> 1, yt = y & 1;
    const int par = comp & 1;

    const __half* Ap = g_Af + (size_t)comp * 256 * KF2;
    const __half* Bp = g_V4 + ((size_t)b * 4 + comp) * ((size_t)KF2 * Cc);
    __half* Fout = (comp < 2) ? g_Fre16 : g_Fim16;
    const int row0 = yt * 128;
    const int NCH = KF2 / 32;

    FragC acc[2][4];
    #pragma unroll
    for (int a = 0; a < 2; a++)
        #pragma unroll
        for (int j = 0; j < 4; j++) wmma::fill_fragment(acc[a][j], 0.0f);

    const int ar = tid >> 2, aq = tid & 3;
    const int br = tid >> 4, bs = tid & 15;

    auto load = [&](int stage, int k0) {
        uint32_t s0 = sb + stage * STAGE;
        size_t ga = (size_t)(row0 + ar) * KF2 + k0 + aq * 8;
        CP16(s0 + ar * 80 + aq * 16, Ap + ga);
        size_t gb = (size_t)(k0 + br) * Cc + bs * 8;
        uint32_t bd = s0 + 10240 + br * 528 + bs * 16;
        CP16(bd, Bp + gb);
        CP16(bd + 256, Bp + gb + 128);
        CP_COMMIT();
    };

    load(0, 0);
    load(1, 32);
    load(2, 64);

    int stage = 0;
    for (int c = 0; c < NCH; c++) {
        if (c + 3 < NCH) {
            int ns = stage + 3; if (ns >= 4) ns -= 4;
            load(ns, (c + 3) * 32);
            CP_WAIT3();
        } else if (c + 2 < NCH) {
            CP_WAIT2();
        } else if (c + 1 < NCH) {
            CP_WAIT1();
        } else {
            CP_WAIT0();
        }
        __syncthreads();

        const char* base = sm + stage * STAGE;
        const __half* As = (const __half*)(base);
        const __half* Bs = (const __half*)(base + 10240);

        #pragma unroll
        for (int ks = 0; ks < 2; ks++) {
            const int kk = ks * 16;
            FragB bf[4];
            #pragma unroll
            for (int j = 0; j < 4; j++)
                wmma::load_matrix_sync(bf[j], Bs + kk * 264 + wn * 64 + j * 16, 264);
            #pragma unroll
            for (int ms = 0; ms < 2; ms++) {
                FragA af;
                wmma::load_matrix_sync(af, As + (wm * 32 + ms * 16) * 40 + kk, 40);
                #pragma unroll
                for (int j = 0; j < 4; j++)
                    wmma::mma_sync(acc[ms][j], af, bf[j], acc[ms][j]);
            }
        }
        __syncthreads();
        stage++; if (stage >= 4) stage = 0;
    }

    float* patch = (float*)sm + warp * 1088;
    #pragma unroll
    for (int ms = 0; ms < 2; ms++) {
        #pragma unroll
        for (int j = 0; j < 4; j++)
            wmma::store_matrix_sync(patch + j * 16, acc[ms][j], 68, wmma::mem_row_major);
        __syncwarp();
        int mpbase = row0 + wm * 32 + ms * 16;
        #pragma unroll
        for (int rr = 0; rr < 16; rr++) {
            float x0 = patch[rr * 68 + lane * 2];
            float x1 = patch[rr * 68 + lane * 2 + 1];
            int m = 2 * (mpbase + rr) + par;
            *(__half2*)(Fout + ((size_t)b * Mm + m) * Cc + wn * 64 + lane * 2)
                = __half2{__float2half(x0), __float2half(x1)};
        }
        __syncwarp();
    }
}

// ---------------------------------------------------------------------------
// Mid WMMA (unchanged from round 15: direct fp32 R read, reg double-buffer).
// ---------------------------------------------------------------------------
#define MAST 16896
#define MBOFF 33792

__global__ __launch_bounds__(256, 2) void mid_wmma(const float* __restrict__ R) {
    extern __shared__ __align__(16) char sm[];
    const uint32_t sb = s2u(sm);
    const int tid = threadIdx.x;
    const int warp = tid >> 5, lane = tid & 31;
    const int m = blockIdx.x;
    const float sc = (m == 0) ? (1.0f / Nn) : (2.0f / Nn);

    __half* Are = (__half*)sm;
    __half* Aim = (__half*)(sm + MAST);

    #pragma unroll
    for (int it = 0; it < 8; it++) {
        int idx = tid + 256 * it;
        int plane = idx >> 10, rem = idx & 1023;
        int row = rem >> 5, seg = rem & 31;
        const __half* src = (plane ? g_Fim16 : g_Fre16)
                            + ((size_t)row * Mm + m) * Cc + seg * 8;
        uint32_t dst = sb + plane * MAST + row * 528 + seg * 16;
        CP16(dst, src);
    }
    CP_COMMIT();

    const int kr = tid >> 3, seg = tid & 7;
    const float* Rm = R + (size_t)m * Cc * Cc;
    float4 rbuf[8];

    auto loadB_regs = [&](int c) {
        const float* src = Rm + (size_t)(c * 32 + kr) * Cc + seg * 32;
        #pragma unroll
        for (int j = 0; j < 8; j++) rbuf[j] = *(const float4*)(src + j * 4);
    };
    auto storeB = [&](int stg) {
        __half* dst = (__half*)(sm + MBOFF + stg * MAST) + kr * 264 + seg * 32;
        #pragma unroll
        for (int j = 0; j < 8; j++) {
            *(__half2*)(dst + j * 4)     = __half2{__float2half(rbuf[j].x * sc),
                                                   __float2half(rbuf[j].y * sc)};
            *(__half2*)(dst + j * 4 + 2) = __half2{__float2half(rbuf[j].z * sc),
                                                   __float2half(rbuf[j].w * sc)};
        }
    };

    loadB_regs(0);
    storeB(0);
    loadB_regs(1);

    FragC accR[2][2], accI[2][2];
    #pragma unroll
    for (int a = 0; a < 2; a++)
        #pragma unroll
        for (int j = 0; j < 2; j++) {
            wmma::fill_fragment(accR[a][j], 0.0f);
            wmma::fill_fragment(accI[a][j], 0.0f);
        }

    CP_WAIT0();
    __syncthreads();

    for (int c = 0; c < 8; c++) {
        if (c + 1 < 8) storeB((c + 1) & 1);

        const __half* Bs = (const __half*)(sm + MBOFF + (c & 1) * MAST);
        #pragma unroll
        for (int ks = 0; ks < 2; ks++) {
            const int kk = c * 32 + ks * 16;
            FragB bf[2];
            #pragma unroll
            for (int j = 0; j < 2; j++)
                wmma::load_matrix_sync(bf[j], Bs + (ks * 16) * 264 + warp * 32 + j * 16, 264);
            #pragma unroll
            for (int ms = 0; ms < 2; ms++) {
                FragA ar_, ai_;
                wmma::load_matrix_sync(ar_, Are + ms * 16 * 264 + kk, 264);
                wmma::load_matrix_sync(ai_, Aim + ms * 16 * 264 + kk, 264);
                #pragma unroll
                for (int j = 0; j < 2; j++) {
                    wmma::mma_sync(accR[ms][j], ar_, bf[j], accR[ms][j]);
                    wmma::mma_sync(accI[ms][j], ai_, bf[j], accI[ms][j]);
                }
            }
        }
        if (c + 2 < 8) loadB_regs(c + 2);
        __syncthreads();
    }

    float* bre = (float*)sm + warp * 2560;
    float* bim = bre + 1280;
    #pragma unroll
    for (int ms = 0; ms < 2; ms++)
        #pragma unroll
        for (int j = 0; j < 2; j++) {
            wmma::store_matrix_sync(bre + ms * 16 * 40 + j * 16, accR[ms][j], 40, wmma::mem_row_major);
            wmma::store_matrix_sync(bim + ms * 16 * 40 + j * 16, accI[ms][j], 40, wmma::mem_row_major);
        }
    __syncwarp();
    const int preP = m & 1;
    const int pimP = 2 + (m & 1);
    const int mrow = m >> 1;
    #pragma unroll 4
    for (int r = 0; r < 32; r++) {
        size_t gre = (((size_t)r * 4 + preP) * 256 + mrow) * Cc + warp * 32 + lane;
        size_t gim = (((size_t)r * 4 + pimP) * 256 + mrow) * Cc + warp * 32 + lane;
        g_G4[gre] = __float2half(bre[r * 40 + lane]);
        g_G4[gim] = __float2half(bim[r * 40 + lane]);
    }
}

// ---------------------------------------------------------------------------
// Inverse WMMA GEMM — full-width CTA, persistent over batches.
// CTA 32(n) x 256(o), 512 threads, 16 warps; loops over 8 batches.
// comp = warp>>2: 0 Ce, 1 Co, 2 Se, 3 So; w4 = warp&3 selects 64-col block.
// Warp tile 32(n) x 64(o): acc[2][4] (2 row-16s x 4 col-16s).
// smem: A resident 4 x [32 x 264] @0 (67584B, loaded once);
//       B 2 stages x (4 x [32 x 264]) @67584 (67584B each) -> total 202752B.
//       epilogue bufs 4 x [32 x 260 fp32] (133120B) overlap B region.
// G4 read exactly once (full o-width per CTA).
// Epilogue: out[n] = v + (Ce+Co) - (Se+So); out[4096-n] = .. + (Se+So) (n>0)
//           out[2048-n] = v + (Ce-Co) + (Se-So); out[2048+n] = .. - (Se-So) (n>0)
// grid: (1, 32, 4) = 128 CTAs.
// ---------------------------------------------------------------------------
#define IA2 67584
#define IB2 67584

__global__ __launch_bounds__(512) void inv_gemm(const float* __restrict__ v,
                                                float* __restrict__ out) {
    extern __shared__ __align__(16) char sm[];
    const uint32_t sb = s2u(sm);
    const int tid = threadIdx.x;
    const int warp = tid >> 5;
    const int comp = warp >> 2;
    const int w4 = warp & 3;             // 64-col block
    const int yt = blockIdx.y, bg = blockIdx.z;
    const int row0 = yt * 32;

    // ---- Resident A: 4 comps x 32 rows x 256 K  (4096 CP16, 8/thread) ----
    #pragma unroll
    for (int it = 0; it < 8; it++) {
        int idx = tid + 512 * it;
        int c = idx >> 10;
        int rem = idx & 1023;
        int r = rem >> 5, seg = rem & 31;
        size_t ga = ((size_t)c << 18) + (size_t)(row0 + r) * 256 + seg * 8;
        uint32_t ad = sb + c * 16896 + r * 528 + seg * 16;
        CP16(ad, g_Ai + ga);
    }
    CP_COMMIT();

    const __half* Asm = (const __half*)sm + comp * 8448;   // elems (16896B/2)

    // B loader: per chunk 4 comps x 32 rows x 32 segs = 4096 CP16, 8/thread.
    auto loadB = [&](int stage, int b, int k0) {
        uint32_t s0 = sb + IA2 + stage * IB2;
        #pragma unroll
        for (int it = 0; it < 8; it++) {
            int idx = tid + 512 * it;
            int c = idx >> 10;
            int rem = idx & 1023;
            int r = rem >> 5, seg = rem & 31;
            size_t gb = (((size_t)b * 4 + c) * 256 + k0 + r) * Cc + seg * 8;
            uint32_t bd = s0 + c * 16896 + r * 528 + seg * 16;
            CP16(bd, g_G4 + gb);
        }
        CP_COMMIT();
    };

    for (int bi = 0; bi < 8; bi++) {
        const int b = bg * 8 + bi;

        FragC acc[2][4];
        #pragma unroll
        for (int a = 0; a < 2; a++)
            #pragma unroll
            for (int j = 0; j < 4; j++) wmma::fill_fragment(acc[a][j], 0.0f);

        loadB(0, b, 0);
        loadB(1, b, 32);

        for (int c = 0; c < 8; c++) {
            if (c < 7) { CP_WAIT1(); } else { CP_WAIT0(); }
            __syncthreads();

            const int stg = c & 1;
            const __half* Bs = (const __half*)(sm + IA2 + stg * IB2
                                               + comp * 16896);
            #pragma unroll
            for (int ks = 0; ks < 2; ks++) {
                const int kk = ks * 16;
                FragB bf[4];
                #pragma unroll
                for (int j = 0; j < 4; j++)
                    wmma::load_matrix_sync(bf[j], Bs + kk * 264 + w4 * 64 + j * 16, 264);
                #pragma unroll
                for (int ms = 0; ms < 2; ms++) {
                    FragA af;
                    wmma::load_matrix_sync(af, Asm + (ms * 16) * 264
                                               + c * 32 + kk, 264);
                    #pragma unroll
                    for (int j = 0; j < 4; j++)
                        wmma::mma_sync(acc[ms][j], af, bf[j], acc[ms][j]);
                }
            }
            __syncthreads();
            if (c + 2 < 8) loadB(stg, b, (c + 2) * 32);
        }

        // ---- Epilogue: 4 comp bufs 32x260 fp32 overlapping the B region ----
        float* bufs = (float*)(sm + IA2);
        float* buf = bufs + comp * 8320;        // 32*260
        #pragma unroll
        for (int ms = 0; ms < 2; ms++)
            #pragma unroll
            for (int j = 0; j < 4; j++)
                wmma::store_matrix_sync(buf + (ms * 16) * 260 + w4 * 64 + j * 16,
                                        acc[ms][j], 260, wmma::mem_row_major);
        __syncthreads();

        const float* Ceb = bufs;
        const float* Cob = bufs + 8320;
        const float* Seb = bufs + 16640;
        const float* Sob = bufs + 24960;
        const size_t rowb = (size_t)b * Nn;

        #pragma unroll
        for (int it = 0; it < 4; it++) {
            int idx = tid + 512 * it;            // 0..2047: 32 rows x 64 float4
            int r = idx >> 6, c4 = idx & 63;
            int off = r * 260 + c4 * 4;
            float4 Ce = *(const float4*)(Ceb + off);
            float4 Co = *(const float4*)(Cob + off);
            float4 Se = *(const float4*)(Seb + off);
            float4 So = *(const float4*)(Sob + off);
            float4 A1 = make_float4(Ce.x + Co.x, Ce.y + Co.y, Ce.z + Co.z, Ce.w + Co.w);
            float4 A2 = make_float4(Se.x + So.x, Se.y + So.y, Se.z + So.z, Se.w + So.w);
            float4 A3 = make_float4(Ce.x - Co.x, Ce.y - Co.y, Ce.z - Co.z, Ce.w - Co.w);
            float4 A4 = make_float4(Se.x - So.x, Se.y - So.y, Se.z - So.z, Se.w - So.w);
            int n = row0 + r;
            int o = c4 * 4;
            {
                size_t i1 = (rowb + n) * Cc + o;
                float4 vv = *(const float4*)(v + i1);
                *(float4*)(out + i1) = make_float4(vv.x + A1.x - A2.x, vv.y + A1.y - A2.y,
                                                   vv.z + A1.z - A2.z, vv.w + A1.w - A2.w);
            }
            if (n > 0) {
                size_t i2 = (rowb + (Nn - n)) * Cc + o;
                float4 vv = *(const float4*)(v + i2);
                *(float4*)(out + i2) = make_float4(vv.x + A1.x + A2.x, vv.y + A1.y + A2.y,
                                                   vv.z + A1.z + A2.z, vv.w + A1.w + A2.w);
            }
            {
                size_t i3 = (rowb + (2048 - n)) * Cc + o;
                float4 vv = *(const float4*)(v + i3);
                *(float4*)(out + i3) = make_float4(vv.x + A3.x + A4.x, vv.y + A3.y + A4.y,
                                                   vv.z + A3.z + A4.z, vv.w + A3.w + A4.w);
            }
            if (n > 0) {
                size_t i4 = (rowb + (2048 + n)) * Cc + o;
                float4 vv = *(const float4*)(v + i4);
                *(float4*)(out + i4) = make_float4(vv.x + A3.x - A4.x, vv.y + A3.y - A4.y,
                                                   vv.z + A3.z - A4.z, vv.w + A3.w - A4.w);
            }
        }
        __syncthreads();   // bufs dead before next batch's loadB reuses region
    }
}

// ---------------------------------------------------------------------------
// rowQ: n = 1024. out[1024] = v + C - S;  out[3072] = v + C + S.
// ---------------------------------------------------------------------------
__global__ __launch_bounds__(64) void rowQ(const float* __restrict__ v,
                                           float* __restrict__ out) {
    const int b = blockIdx.x;
    const int o = threadIdx.x * 4;
    float c0 = 0.f, c1 = 0.f, c2 = 0.f, c3 = 0.f;
    float s0 = 0.f, s1 = 0.f, s2 = 0.f, s3 = 0.f;
    const __half* GreE = g_G4 + ((size_t)b * 4 + 0) * 65536;
    const __half* GimO = g_G4 + ((size_t)b * 4 + 3) * 65536;
    #pragma unroll 8
    for (int mp = 0; mp < 256; mp++) {
        float sgn = (mp & 1) ? -1.0f : 1.0f;
        const __half* gr = GreE + (size_t)mp * Cc + o;
        const __half* gi = GimO + (size_t)mp * Cc + o;
        __half2 ra = *(const __half2*)(gr), rb = *(const __half2*)(gr + 2);
        __half2 ia = *(const __half2*)(gi), ib = *(const __half2*)(gi + 2);
        c0 += sgn * __half2float(ra.x); c1 += sgn * __half2float(ra.y);
        c2 += sgn * __half2float(rb.x); c3 += sgn * __half2float(rb.y);
        s0 += sgn * __half2float(ia.x); s1 += sgn * __half2float(ia.y);
        s2 += sgn * __half2float(ib.x); s3 += sgn * __half2float(ib.y);
    }
    size_t i1 = ((size_t)b * Nn + 1024) * Cc + o;
    size_t i2 = ((size_t)b * Nn + 3072) * Cc + o;
    float4 v1 = *(const float4*)(v + i1);
    float4 v2 = *(const float4*)(v + i2);
    *(float4*)(out + i1) = make_float4(v1.x + c0 - s0, v1.y + c1 - s1,
                                       v1.z + c2 - s2, v1.w + c3 - s3);
    *(float4*)(out + i2) = make_float4(v2.x + c0 + s0, v2.y + c1 + s1,
                                       v2.z + c2 + s2, v2.w + c3 + s3);
}

// ---------------------------------------------------------------------------
extern "C" void kernel_launch(void* const* d_in, const int* in_sizes, int n_in,
                              void* d_out, int out_size) {
    const float* v = (const float*)d_in[0];
    const float* R = (const float*)d_in[1];
    float* out = (float*)d_out;

    const int smF = 4 * STAGE;              // 108544
    const int smMid = 81920;
    const int smInv = IA2 + 2 * IB2;        // 202752
    cudaFuncSetAttribute(fwd_gemm, cudaFuncAttributeMaxDynamicSharedMemorySize, smF);
    cudaFuncSetAttribute(mid_wmma, cudaFuncAttributeMaxDynamicSharedMemorySize, smMid);
    cudaFuncSetAttribute(inv_gemm, cudaFuncAttributeMaxDynamicSharedMemorySize, smInv);

    prep_all<<<PREP_BLOCKS, 256>>>(v);
    fwd_gemm<<<dim3(1, 8, Bb), 512, smF>>>();
    mid_wmma<<<Mm, 256, smMid>>>(R);
    inv_gemm<<<dim3(1, 32, 4), 512, smInv>>>(v, out);
    rowQ<<<Bb, 64>>>(v, out);
}

// round 17
// speedup vs baseline: 1.0959x; 1.0959x over previous
#include <cuda_runtime.h>
#include <cuda_fp16.h>
#include <mma.h>
#include <cstdint>

using namespace nvcuda;

#define Bb 32
#define Nn 4096
#define Mm 512
#define Cc 256
#define KF2 1056           // double-folded forward K (0..1024 data, pad to 33*32)

// ---------------------------------------------------------------------------
// Global scratch (static __device__ — no runtime allocation)
// ---------------------------------------------------------------------------
__device__ __align__(16) __half g_Af[(size_t)4 * 256 * KF2];
__device__ __align__(16) __half g_V4[(size_t)Bb * 4 * KF2 * Cc];
__device__ __align__(16) __half g_Ai[(size_t)4 * 1024 * 256];
__device__ __align__(16) __half g_Fre16[(size_t)Bb * Mm * Cc];
__device__ __align__(16) __half g_Fim16[(size_t)Bb * Mm * Cc];
__device__ __align__(16) __half g_G4[(size_t)Bb * 4 * 256 * 256];

// ---------------------------------------------------------------------------
__device__ __forceinline__ uint32_t s2u(const void* p) {
    uint32_t a;
    asm("{ .reg .u64 t; cvta.to.shared.u64 t, %1; cvt.u32.u64 %0, t; }"
        : "=r"(a) : "l"(p));
    return a;
}

#define CP16(dst, src) \
    asm volatile("cp.async.cg.shared.global [%0], [%1], 16;" :: "r"(dst), "l"(src))
#define CP_COMMIT() asm volatile("cp.async.commit_group;")
#define CP_WAIT3()  asm volatile("cp.async.wait_group 3;" ::: "memory")
#define CP_WAIT2()  asm volatile("cp.async.wait_group 2;" ::: "memory")
#define CP_WAIT1()  asm volatile("cp.async.wait_group 1;" ::: "memory")
#define CP_WAIT0()  asm volatile("cp.async.wait_group 0;" ::: "memory")

typedef wmma::fragment<wmma::matrix_a, 16, 16, 16, __half, wmma::row_major> FragA;
typedef wmma::fragment<wmma::matrix_b, 16, 16, 16, __half, wmma::row_major> FragB;
typedef wmma::fragment<wmma::accumulator, 16, 16, 16, float> FragC;

// ---------------------------------------------------------------------------
// Fused prep (one launch, permuted block order; pack_R removed).
//   [0, 4224)       genA_fwd
//   [4224, 8320)    genA_inv
//   [8320, 16768)   packV4
// ---------------------------------------------------------------------------
#define PREP_BLOCKS 16768

__global__ __launch_bounds__(256) void prep_all(const float* __restrict__ v) {
    const int tid = threadIdx.x;
    unsigned u = (unsigned)(((unsigned long long)blockIdx.x * 9871ull) % PREP_BLOCKS);

    if (u < 4224u) {
        int idx = (int)u * 256 + tid;
        int comp = idx / (256 * KF2);
        int rem = idx - comp * (256 * KF2);
        int mp = rem / KF2, k = rem - mp * KF2;
        int m = 2 * mp + (comp & 1);
        float val = 0.0f;
        if (k <= 1024) {
            int t = (int)(((long long)m * k) & (Nn - 1));
            float s, c;
            sincospif((float)t * (1.0f / 2048.0f), &s, &c);
            val = (comp < 2) ? c : -s;
        }
        g_Af[idx] = __float2half(val);
    } else if (u < 8320u) {
        int idx = (int)(u - 4224u) * 256 + tid;
        int comp = idx >> 18;
        int rem = idx & 262143;
        int n = rem >> 8, mp = rem & 255;
        int m = 2 * mp + (comp & 1);
        int t = (int)(((long long)m * n) & (Nn - 1));
        float s, c;
        sincospif((float)t * (1.0f / 2048.0f), &s, &c);
        g_Ai[idx] = __float2half((comp < 2) ? c : s);
    } else {
        size_t idx4 = (size_t)(u - 8320u) * 256 + tid;
        int b = (int)(idx4 / (KF2 * 64));
        int rem = (int)(idx4 - (size_t)b * (KF2 * 64));
        int k = rem >> 6, i = (rem & 63) * 4;
        float4 pp, pm, mm_, mp;
        const float* vb = v + (size_t)b * Nn * Cc;
        if (k == 0) {
            float4 a = *(const float4*)(vb + i);
            float4 d = *(const float4*)(vb + (size_t)2048 * Cc + i);
            pp = make_float4(a.x + d.x, a.y + d.y, a.z + d.z, a.w + d.w);
            pm = make_float4(a.x - d.x, a.y - d.y, a.z - d.z, a.w - d.w);
            mm_ = make_float4(0.f, 0.f, 0.f, 0.f);
            mp = mm_;
        } else if (k < 1024) {
            float4 a = *(const float4*)(vb + (size_t)k * Cc + i);
            float4 bq = *(const float4*)(vb + (size_t)(Nn - k) * Cc + i);
            float4 c = *(const float4*)(vb + (size_t)(2048 - k) * Cc + i);
            float4 d = *(const float4*)(vb + (size_t)(2048 + k) * Cc + i);
            pp = make_float4(a.x + bq.x + c.x + d.x, a.y + bq.y + c.y + d.y,
                             a.z + bq.z + c.z + d.z, a.w + bq.w + c.w + d.w);
            pm = make_float4(a.x + bq.x - c.x - d.x, a.y + bq.y - c.y - d.y,
                             a.z + bq.z - c.z - d.z, a.w + bq.w - c.w - d.w);
            mm_ = make_float4(a.x - bq.x - c.x + d.x, a.y - bq.y - c.y + d.y,
                              a.z - bq.z - c.z + d.z, a.w - bq.w - c.w + d.w);
            mp = make_float4(a.x - bq.x + c.x - d.x, a.y - bq.y + c.y - d.y,
                             a.z - bq.z + c.z - d.z, a.w - bq.w + c.w - d.w);
        } else if (k == 1024) {
            float4 a = *(const float4*)(vb + (size_t)1024 * Cc + i);
            float4 d = *(const float4*)(vb + (size_t)3072 * Cc + i);
            pp = make_float4(a.x + d.x, a.y + d.y, a.z + d.z, a.w + d.w);
            mp = make_float4(a.x - d.x, a.y - d.y, a.z - d.z, a.w - d.w);
            pm = make_float4(0.f, 0.f, 0.f, 0.f);
            mm_ = pm;
        } else {
            pp = make_float4(0.f, 0.f, 0.f, 0.f);
            pm = pp; mm_ = pp; mp = pp;
        }
        size_t pbase = ((size_t)b * 4) * (KF2 * (size_t)Cc) + (size_t)k * Cc + i;
        const size_t PS = (size_t)KF2 * Cc;
        *(__half2*)(g_V4 + pbase)              = __half2{__float2half(pp.x), __float2half(pp.y)};
        *(__half2*)(g_V4 + pbase + 2)          = __half2{__float2half(pp.z), __float2half(pp.w)};
        *(__half2*)(g_V4 + pbase + PS)         = __half2{__float2half(pm.x), __float2half(pm.y)};
        *(__half2*)(g_V4 + pbase + PS + 2)     = __half2{__float2half(pm.z), __float2half(pm.w)};
        *(__half2*)(g_V4 + pbase + 2 * PS)     = __half2{__float2half(mm_.x), __float2half(mm_.y)};
        *(__half2*)(g_V4 + pbase + 2 * PS + 2) = __half2{__float2half(mm_.z), __float2half(mm_.w)};
        *(__half2*)(g_V4 + pbase + 3 * PS)     = __half2{__float2half(mp.x), __float2half(mp.y)};
        *(__half2*)(g_V4 + pbase + 3 * PS + 2) = __half2{__float2half(mp.z), __float2half(mp.w)};
    }
}

// ---------------------------------------------------------------------------
// Forward WMMA GEMM (double-folded). CTA 128(m') x 256(i), 512 threads,
// warp tile 32x64, 4-stage cp.async, K=1056.
// ---------------------------------------------------------------------------
#define STAGE 27136

__global__ __launch_bounds__(512) void fwd_gemm() {
    extern __shared__ __align__(16) char sm[];
    const uint32_t sb = s2u(sm);
    const int tid = threadIdx.x;
    const int warp = tid >> 5, lane = tid & 31;
    const int wm = warp >> 2, wn = warp & 3;
    const int b = blockIdx.z;
    const int y = blockIdx.y;
    const int comp = y >> 1, yt = y & 1;
    const int par = comp & 1;

    const __half* Ap = g_Af + (size_t)comp * 256 * KF2;
    const __half* Bp = g_V4 + ((size_t)b * 4 + comp) * ((size_t)KF2 * Cc);
    __half* Fout = (comp < 2) ? g_Fre16 : g_Fim16;
    const int row0 = yt * 128;
    const int NCH = KF2 / 32;

    FragC acc[2][4];
    #pragma unroll
    for (int a = 0; a < 2; a++)
        #pragma unroll
        for (int j = 0; j < 4; j++) wmma::fill_fragment(acc[a][j], 0.0f);

    const int ar = tid >> 2, aq = tid & 3;
    const int br = tid >> 4, bs = tid & 15;

    auto load = [&](int stage, int k0) {
        uint32_t s0 = sb + stage * STAGE;
        size_t ga = (size_t)(row0 + ar) * KF2 + k0 + aq * 8;
        CP16(s0 + ar * 80 + aq * 16, Ap + ga);
        size_t gb = (size_t)(k0 + br) * Cc + bs * 8;
        uint32_t bd = s0 + 10240 + br * 528 + bs * 16;
        CP16(bd, Bp + gb);
        CP16(bd + 256, Bp + gb + 128);
        CP_COMMIT();
    };

    load(0, 0);
    load(1, 32);
    load(2, 64);

    int stage = 0;
    for (int c = 0; c < NCH; c++) {
        if (c + 3 < NCH) {
            int ns = stage + 3; if (ns >= 4) ns -= 4;
            load(ns, (c + 3) * 32);
            CP_WAIT3();
        } else if (c + 2 < NCH) {
            CP_WAIT2();
        } else if (c + 1 < NCH) {
            CP_WAIT1();
        } else {
            CP_WAIT0();
        }
        __syncthreads();

        const char* base = sm + stage * STAGE;
        const __half* As = (const __half*)(base);
        const __half* Bs = (const __half*)(base + 10240);

        #pragma unroll
        for (int ks = 0; ks < 2; ks++) {
            const int kk = ks * 16;
            FragB bf[4];
            #pragma unroll
            for (int j = 0; j < 4; j++)
                wmma::load_matrix_sync(bf[j], Bs + kk * 264 + wn * 64 + j * 16, 264);
            #pragma unroll
            for (int ms = 0; ms < 2; ms++) {
                FragA af;
                wmma::load_matrix_sync(af, As + (wm * 32 + ms * 16) * 40 + kk, 40);
                #pragma unroll
                for (int j = 0; j < 4; j++)
                    wmma::mma_sync(acc[ms][j], af, bf[j], acc[ms][j]);
            }
        }
        __syncthreads();
        stage++; if (stage >= 4) stage = 0;
    }

    float* patch = (float*)sm + warp * 1088;
    #pragma unroll
    for (int ms = 0; ms < 2; ms++) {
        #pragma unroll
        for (int j = 0; j < 4; j++)
            wmma::store_matrix_sync(patch + j * 16, acc[ms][j], 68, wmma::mem_row_major);
        __syncwarp();
        int mpbase = row0 + wm * 32 + ms * 16;
        #pragma unroll
        for (int rr = 0; rr < 16; rr++) {
            float x0 = patch[rr * 68 + lane * 2];
            float x1 = patch[rr * 68 + lane * 2 + 1];
            int m = 2 * (mpbase + rr) + par;
            *(__half2*)(Fout + ((size_t)b * Mm + m) * Cc + wn * 64 + lane * 2)
                = __half2{__float2half(x0), __float2half(x1)};
        }
        __syncwarp();
    }
}

// ---------------------------------------------------------------------------
// Mid WMMA (direct fp32 R read, reg double-buffer).
// ---------------------------------------------------------------------------
#define MAST 16896
#define MBOFF 33792

__global__ __launch_bounds__(256, 2) void mid_wmma(const float* __restrict__ R) {
    extern __shared__ __align__(16) char sm[];
    const uint32_t sb = s2u(sm);
    const int tid = threadIdx.x;
    const int warp = tid >> 5, lane = tid & 31;
    const int m = blockIdx.x;
    const float sc = (m == 0) ? (1.0f / Nn) : (2.0f / Nn);

    __half* Are = (__half*)sm;
    __half* Aim = (__half*)(sm + MAST);

    #pragma unroll
    for (int it = 0; it < 8; it++) {
        int idx = tid + 256 * it;
        int plane = idx >> 10, rem = idx & 1023;
        int row = rem >> 5, seg = rem & 31;
        const __half* src = (plane ? g_Fim16 : g_Fre16)
                            + ((size_t)row * Mm + m) * Cc + seg * 8;
        uint32_t dst = sb + plane * MAST + row * 528 + seg * 16;
        CP16(dst, src);
    }
    CP_COMMIT();

    const int kr = tid >> 3, seg = tid & 7;
    const float* Rm = R + (size_t)m * Cc * Cc;
    float4 rbuf[8];

    auto loadB_regs = [&](int c) {
        const float* src = Rm + (size_t)(c * 32 + kr) * Cc + seg * 32;
        #pragma unroll
        for (int j = 0; j < 8; j++) rbuf[j] = *(const float4*)(src + j * 4);
    };
    auto storeB = [&](int stg) {
        __half* dst = (__half*)(sm + MBOFF + stg * MAST) + kr * 264 + seg * 32;
        #pragma unroll
        for (int j = 0; j < 8; j++) {
            *(__half2*)(dst + j * 4)     = __half2{__float2half(rbuf[j].x * sc),
                                                   __float2half(rbuf[j].y * sc)};
            *(__half2*)(dst + j * 4 + 2) = __half2{__float2half(rbuf[j].z * sc),
                                                   __float2half(rbuf[j].w * sc)};
        }
    };

    loadB_regs(0);
    storeB(0);
    loadB_regs(1);

    FragC accR[2][2], accI[2][2];
    #pragma unroll
    for (int a = 0; a < 2; a++)
        #pragma unroll
        for (int j = 0; j < 2; j++) {
            wmma::fill_fragment(accR[a][j], 0.0f);
            wmma::fill_fragment(accI[a][j], 0.0f);
        }

    CP_WAIT0();
    __syncthreads();

    for (int c = 0; c < 8; c++) {
        if (c + 1 < 8) storeB((c + 1) & 1);

        const __half* Bs = (const __half*)(sm + MBOFF + (c & 1) * MAST);
        #pragma unroll
        for (int ks = 0; ks < 2; ks++) {
            const int kk = c * 32 + ks * 16;
            FragB bf[2];
            #pragma unroll
            for (int j = 0; j < 2; j++)
                wmma::load_matrix_sync(bf[j], Bs + (ks * 16) * 264 + warp * 32 + j * 16, 264);
            #pragma unroll
            for (int ms = 0; ms < 2; ms++) {
                FragA ar_, ai_;
                wmma::load_matrix_sync(ar_, Are + ms * 16 * 264 + kk, 264);
                wmma::load_matrix_sync(ai_, Aim + ms * 16 * 264 + kk, 264);
                #pragma unroll
                for (int j = 0; j < 2; j++) {
                    wmma::mma_sync(accR[ms][j], ar_, bf[j], accR[ms][j]);
                    wmma::mma_sync(accI[ms][j], ai_, bf[j], accI[ms][j]);
                }
            }
        }
        if (c + 2 < 8) loadB_regs(c + 2);
        __syncthreads();
    }

    float* bre = (float*)sm + warp * 2560;
    float* bim = bre + 1280;
    #pragma unroll
    for (int ms = 0; ms < 2; ms++)
        #pragma unroll
        for (int j = 0; j < 2; j++) {
            wmma::store_matrix_sync(bre + ms * 16 * 40 + j * 16, accR[ms][j], 40, wmma::mem_row_major);
            wmma::store_matrix_sync(bim + ms * 16 * 40 + j * 16, accI[ms][j], 40, wmma::mem_row_major);
        }
    __syncwarp();
    const int preP = m & 1;
    const int pimP = 2 + (m & 1);
    const int mrow = m >> 1;
    #pragma unroll 4
    for (int r = 0; r < 32; r++) {
        size_t gre = (((size_t)r * 4 + preP) * 256 + mrow) * Cc + warp * 32 + lane;
        size_t gim = (((size_t)r * 4 + pimP) * 256 + mrow) * Cc + warp * 32 + lane;
        g_G4[gre] = __float2half(bre[r * 40 + lane]);
        g_G4[gim] = __float2half(bim[r * 40 + lane]);
    }
}

// ---------------------------------------------------------------------------
// Inverse WMMA GEMM, persistent over batches, A (twiddles) smem-resident
// (round-14/15 proven config, 138 µs).
// CTA 64(n) x 128(o), 512 threads; loops over 8 batches. grid (2,16,4).
// ---------------------------------------------------------------------------
#define IA_BYTES 135168
#define IB_STAGE 34816

__global__ __launch_bounds__(512) void inv_gemm(const float* __restrict__ v,
                                                float* __restrict__ out) {
    extern __shared__ __align__(16) char sm[];
    const uint32_t sb = s2u(sm);
    const int tid = threadIdx.x;
    const int warp = tid >> 5;
    const int comp = warp >> 2;
    const int w4 = warp & 3;
    const int wm = w4 >> 1, wn = w4 & 1;
    const int colt = blockIdx.x, yt = blockIdx.y, bg = blockIdx.z;
    const int row0 = yt * 64, c0 = colt * 128;

    #pragma unroll
    for (int it = 0; it < 16; it++) {
        int idx = tid + 512 * it;
        int c = idx >> 11;
        int rem = idx & 2047;
        int r = rem >> 5, seg = rem & 31;
        size_t ga = ((size_t)c << 18) + (size_t)(row0 + r) * 256 + seg * 8;
        uint32_t ad = sb + c * 33792 + r * 528 + seg * 16;
        CP16(ad, g_Ai + ga);
    }
    CP_COMMIT();

    const __half* Asm = (const __half*)sm + comp * 16896;

    auto loadB = [&](int stage, int b, int k0) {
        uint32_t s0 = sb + IA_BYTES + stage * IB_STAGE;
        #pragma unroll
        for (int it = 0; it < 4; it++) {
            int idx = tid + 512 * it;
            int c = idx >> 9;
            int rem = idx & 511;
            int r = rem >> 4, seg = rem & 15;
            size_t gb = (((size_t)b * 4 + c) * 256 + k0 + r) * Cc + c0 + seg * 8;
            uint32_t bd = s0 + c * 8704 + r * 272 + seg * 16;
            CP16(bd, g_G4 + gb);
        }
        CP_COMMIT();
    };

    for (int bi = 0; bi < 8; bi++) {
        const int b = bg * 8 + bi;

        FragC acc[2][4];
        #pragma unroll
        for (int a = 0; a < 2; a++)
            #pragma unroll
            for (int j = 0; j < 4; j++) wmma::fill_fragment(acc[a][j], 0.0f);

        loadB(0, b, 0);
        loadB(1, b, 32);

        for (int c = 0; c < 8; c++) {
            if (c < 7) { CP_WAIT1(); } else { CP_WAIT0(); }
            __syncthreads();

            const int stg = c & 1;
            const __half* Bs = (const __half*)(sm + IA_BYTES + stg * IB_STAGE
                                               + comp * 8704);
            #pragma unroll
            for (int ks = 0; ks < 2; ks++) {
                const int kk = ks * 16;
                FragB bf[4];
                #pragma unroll
                for (int j = 0; j < 4; j++)
                    wmma::load_matrix_sync(bf[j], Bs + kk * 136 + wn * 64 + j * 16, 136);
                #pragma unroll
                for (int ms = 0; ms < 2; ms++) {
                    FragA af;
                    wmma::load_matrix_sync(af, Asm + (wm * 32 + ms * 16) * 264
                                               + c * 32 + kk, 264);
                    #pragma unroll
                    for (int j = 0; j < 4; j++)
                        wmma::mma_sync(acc[ms][j], af, bf[j], acc[ms][j]);
                }
            }
            __syncthreads();
            if (c + 2 < 8) loadB(stg, b, (c + 2) * 32);
        }

        float* bufs = (float*)(sm + IA_BYTES);
        float* buf = bufs + comp * 4352;
        const float* Ceb = bufs;
        const float* Cob = bufs + 4352;
        const float* Seb = bufs + 8704;
        const float* Sob = bufs + 13056;
        const size_t rowb = (size_t)b * Nn;

        #pragma unroll
        for (int h = 0; h < 2; h++) {
            if (wn == h) {
                #pragma unroll
                for (int ms = 0; ms < 2; ms++)
                    #pragma unroll
                    for (int j = 0; j < 4; j++)
                        wmma::store_matrix_sync(buf + (wm * 32 + ms * 16) * 68 + j * 16,
                                                acc[ms][j], 68, wmma::mem_row_major);
            }
            __syncthreads();

            #pragma unroll
            for (int it = 0; it < 2; it++) {
                int idx = tid + 512 * it;
                int r = idx >> 4, c4 = idx & 15;
                int off = r * 68 + c4 * 4;
                float4 Ce = *(const float4*)(Ceb + off);
                float4 Co = *(const float4*)(Cob + off);
                float4 Se = *(const float4*)(Seb + off);
                float4 So = *(const float4*)(Sob + off);
                float4 A1 = make_float4(Ce.x + Co.x, Ce.y + Co.y, Ce.z + Co.z, Ce.w + Co.w);
                float4 A2 = make_float4(Se.x + So.x, Se.y + So.y, Se.z + So.z, Se.w + So.w);
                float4 A3 = make_float4(Ce.x - Co.x, Ce.y - Co.y, Ce.z - Co.z, Ce.w - Co.w);
                float4 A4 = make_float4(Se.x - So.x, Se.y - So.y, Se.z - So.z, Se.w - So.w);
                int n = row0 + r;
                int o = c0 + h * 64 + c4 * 4;
                {
                    size_t i1 = (rowb + n) * Cc + o;
                    float4 vv = *(const float4*)(v + i1);
                    *(float4*)(out + i1) = make_float4(vv.x + A1.x - A2.x, vv.y + A1.y - A2.y,
                                                       vv.z + A1.z - A2.z, vv.w + A1.w - A2.w);
                }
                if (n > 0) {
                    size_t i2 = (rowb + (Nn - n)) * Cc + o;
                    float4 vv = *(const float4*)(v + i2);
                    *(float4*)(out + i2) = make_float4(vv.x + A1.x + A2.x, vv.y + A1.y + A2.y,
                                                       vv.z + A1.z + A2.z, vv.w + A1.w + A2.w);
                }
                {
                    size_t i3 = (rowb + (2048 - n)) * Cc + o;
                    float4 vv = *(const float4*)(v + i3);
                    *(float4*)(out + i3) = make_float4(vv.x + A3.x + A4.x, vv.y + A3.y + A4.y,
                                                       vv.z + A3.z + A4.z, vv.w + A3.w + A4.w);
                }
                if (n > 0) {
                    size_t i4 = (rowb + (2048 + n)) * Cc + o;
                    float4 vv = *(const float4*)(v + i4);
                    *(float4*)(out + i4) = make_float4(vv.x + A3.x - A4.x, vv.y + A3.y - A4.y,
                                                       vv.z + A3.z - A4.z, vv.w + A3.w - A4.w);
                }
            }
            __syncthreads();
        }
    }
}

// ---------------------------------------------------------------------------
// rowQ: n = 1024. out[1024] = v + C - S;  out[3072] = v + C + S.
// ---------------------------------------------------------------------------
__global__ __launch_bounds__(64) void rowQ(const float* __restrict__ v,
                                           float* __restrict__ out) {
    const int b = blockIdx.x;
    const int o = threadIdx.x * 4;
    float c0 = 0.f, c1 = 0.f, c2 = 0.f, c3 = 0.f;
    float s0 = 0.f, s1 = 0.f, s2 = 0.f, s3 = 0.f;
    const __half* GreE = g_G4 + ((size_t)b * 4 + 0) * 65536;
    const __half* GimO = g_G4 + ((size_t)b * 4 + 3) * 65536;
    #pragma unroll 8
    for (int mp = 0; mp < 256; mp++) {
        float sgn = (mp & 1) ? -1.0f : 1.0f;
        const __half* gr = GreE + (size_t)mp * Cc + o;
        const __half* gi = GimO + (size_t)mp * Cc + o;
        __half2 ra = *(const __half2*)(gr), rb = *(const __half2*)(gr + 2);
        __half2 ia = *(const __half2*)(gi), ib = *(const __half2*)(gi + 2);
        c0 += sgn * __half2float(ra.x); c1 += sgn * __half2float(ra.y);
        c2 += sgn * __half2float(rb.x); c3 += sgn * __half2float(rb.y);
        s0 += sgn * __half2float(ia.x); s1 += sgn * __half2float(ia.y);
        s2 += sgn * __half2float(ib.x); s3 += sgn * __half2float(ib.y);
    }
    size_t i1 = ((size_t)b * Nn + 1024) * Cc + o;
    size_t i2 = ((size_t)b * Nn + 3072) * Cc + o;
    float4 v1 = *(const float4*)(v + i1);
    float4 v2 = *(const float4*)(v + i2);
    *(float4*)(out + i1) = make_float4(v1.x + c0 - s0, v1.y + c1 - s1,
                                       v1.z + c2 - s2, v1.w + c3 - s3);
    *(float4*)(out + i2) = make_float4(v2.x + c0 + s0, v2.y + c1 + s1,
                                       v2.z + c2 + s2, v2.w + c3 + s3);
}

// ---------------------------------------------------------------------------
extern "C" void kernel_launch(void* const* d_in, const int* in_sizes, int n_in,
                              void* d_out, int out_size) {
    const float* v = (const float*)d_in[0];
    const float* R = (const float*)d_in[1];
    float* out = (float*)d_out;

    const int smF = 4 * STAGE;              // 108544
    const int smMid = 81920;
    const int smInv = IA_BYTES + 69632;     // 204800
    cudaFuncSetAttribute(fwd_gemm, cudaFuncAttributeMaxDynamicSharedMemorySize, smF);
    cudaFuncSetAttribute(mid_wmma, cudaFuncAttributeMaxDynamicSharedMemorySize, smMid);
    cudaFuncSetAttribute(inv_gemm, cudaFuncAttributeMaxDynamicSharedMemorySize, smInv);

    prep_all<<<PREP_BLOCKS, 256>>>(v);
    fwd_gemm<<<dim3(1, 8, Bb), 512, smF>>>();
    mid_wmma<<<Mm, 256, smMid>>>(R);
    rowQ<<<Bb, 64>>>(v, out);                      // independent of inv; fills ramp
    inv_gemm<<<dim3(2, 16, 4), 512, smInv>>>(v, out);
}